// round 13
// baseline (speedup 1.0000x reference)
#include <cuda_runtime.h>
#include <cstdint>

// ROI pooling (bilinear, half-pixel centers, clamped to crop).
//   img:  (1, 1024, 1024, 256) float32, NHWC
//   rois: (1, 300, 4) float32 (x0, y0, w, h) -> int
//   out:  (1, 300, 7, 7, 256) float32
//
// FINAL (R8/R10/R12 configuration; 10.72-10.75us across 3 benches).
// 75MB irreducible traffic (60MB distinct corner rows + 15MB out) at
// ~7.0TB/s effective = ~87% of HBM spec -> at the traffic roofline.
//  - exact-fit 224-thread blocks: one warp per (pool-row x 1KB channel row)
//  - 32B ld.global.nc.L2::evict_last reads, default write-back stores
//  - 32-bit address math, regs=32, no smem
// Falsified levers (12 rounds): MLP 4/8/12 per thread, occupancy 30-93%,
// cp.async (LDGSTS), cp.async.bulk (TMA), .cs streaming stores, L1 carveout,
// persistent-CTA double-buffer pipeline.

#define POOL 7
#define IMG_W 1024
#define CF 256          // channels (floats)

struct F8 { float f[8]; };   // 32 bytes

__device__ __forceinline__ F8 ldg_keep32(const float* p) {
    uint64_t u0, u1, u2, u3;
    asm volatile("ld.global.nc.L2::evict_last.v4.b64 {%0,%1,%2,%3}, [%4];"
                 : "=l"(u0), "=l"(u1), "=l"(u2), "=l"(u3) : "l"(p));
    F8 r;
    *reinterpret_cast<uint64_t*>(&r.f[0]) = u0;
    *reinterpret_cast<uint64_t*>(&r.f[2]) = u1;
    *reinterpret_cast<uint64_t*>(&r.f[4]) = u2;
    *reinterpret_cast<uint64_t*>(&r.f[6]) = u3;
    return r;
}

__device__ __forceinline__ void stg32(float* p, const float* v) {
    const uint64_t* u = reinterpret_cast<const uint64_t*>(v);
    asm volatile("st.global.v4.b64 [%0], {%1,%2,%3,%4};"
                 :: "l"(p), "l"(u[0]), "l"(u[1]), "l"(u[2]), "l"(u[3])
                 : "memory");
}

__global__ __launch_bounds__(224) void roi_pool_kernel(
    const float*  __restrict__ img,    // (H*W*256) floats
    const float4* __restrict__ rois4,  // (300) float4 = (x0,y0,w,h)
    float*        __restrict__ out)    // (300*49*256) floats
{
    const int roi = blockIdx.y;
    const int px  = blockIdx.x;      // 0..6
    const int py  = threadIdx.y;     // 0..6 (one warp per pool row)

    const float4 rp = __ldg(rois4 + roi);
    const int x0 = (int)rp.x;
    const int y0 = (int)rp.y;
    const int w  = (int)rp.z;
    const int h  = (int)rp.w;

    // Sample coords, exactly as reference: c = (i+0.5)*(size/P) - 0.5, clamped.
    float cy = ((float)py + 0.5f) * ((float)h / (float)POOL) - 0.5f;
    cy = fminf(fmaxf(cy, 0.0f), (float)h - 1.0f);
    float cx = ((float)px + 0.5f) * ((float)w / (float)POOL) - 0.5f;
    cx = fminf(fmaxf(cx, 0.0f), (float)w - 1.0f);

    const int ylo = (int)cy;
    const int xlo = (int)cx;
    const int yhi = min(ylo + 1, h - 1);
    const int xhi = min(xlo + 1, w - 1);
    const float fy = cy - (float)ylo;
    const float fx = cx - (float)xlo;

    const float w00 = (1.0f - fy) * (1.0f - fx);
    const float w01 = (1.0f - fy) * fx;
    const float w10 = fy * (1.0f - fx);
    const float w11 = fy * fx;

    // Float offsets fit in 32 bits (img = 2^28 floats).
    const unsigned r_lo = (unsigned)(y0 + ylo) * (IMG_W * CF);
    const unsigned r_hi = (unsigned)(y0 + yhi) * (IMG_W * CF);
    const unsigned cL   = (unsigned)(x0 + xlo) * CF;
    const unsigned cR   = (unsigned)(x0 + xhi) * CF;

    const unsigned c8 = (unsigned)threadIdx.x * 8;   // lane * 8 floats (32B)

    const F8 v00 = ldg_keep32(img + r_lo + cL + c8);
    const F8 v01 = ldg_keep32(img + r_lo + cR + c8);
    const F8 v10 = ldg_keep32(img + r_hi + cL + c8);
    const F8 v11 = ldg_keep32(img + r_hi + cR + c8);

    float o[8];
    #pragma unroll
    for (int i = 0; i < 8; i++)
        o[i] = v00.f[i] * w00 + v01.f[i] * w01 + v10.f[i] * w10 + v11.f[i] * w11;

    stg32(out + ((unsigned)roi * (POOL * POOL) + (unsigned)(py * POOL + px)) * CF + c8, o);
}

extern "C" void kernel_launch(void* const* d_in, const int* in_sizes, int n_in,
                              void* d_out, int out_size)
{
    const float*  img   = (const float*)d_in[0];
    const float4* rois4 = (const float4*)d_in[1];
    float* o = (float*)d_out;

    dim3 block(32, POOL, 1);    // 32 lanes x 7 pool rows = 224 (exact fit)
    dim3 grid(POOL, 300, 1);    // px x roi
    roi_pool_kernel<<<grid, block>>>(img, rois4, o);
}

// round 14
// speedup vs baseline: 1.0456x; 1.0456x over previous
#include <cuda_runtime.h>
#include <cstdint>

// ROI pooling (bilinear, half-pixel centers, clamped to crop).
//   img:  (1, 1024, 1024, 256) float32, NHWC
//   rois: (1, 300, 4) float32 (x0, y0, w, h) -> int
//   out:  (1, 300, 7, 7, 256) float32
//
// FINAL — converged configuration (benched 10.72/10.75/10.75/11.01us).
// Bound analysis: 74MB traffic (60MB provably-distinct corner rows + 15MB
// out) through the path-independent LTS cap (~6300 B/cyc) = ~10.5us floor;
// measured 10.72us best. At the cap, instruction/pipeline choice cannot
// matter — confirmed empirically across 13 rounds:
//   neutral-or-worse: MLP 4/8/12, occupancy 30-93%, cp.async, TMA bulk,
//   .cs stores, L2 evict policies, L1 carveout, persistent pipeline (-38%).
// Winning config: exact-fit 224-thread blocks (warp = pool-row x 1KB channel
// row), 32B v4.b64 evict_last reads, default write-back stores, 32-bit
// addressing, regs=32, no smem.

#define POOL 7
#define IMG_W 1024
#define CF 256          // channels (floats)

struct F8 { float f[8]; };   // 32 bytes

__device__ __forceinline__ F8 ldg_keep32(const float* p) {
    uint64_t u0, u1, u2, u3;
    asm volatile("ld.global.nc.L2::evict_last.v4.b64 {%0,%1,%2,%3}, [%4];"
                 : "=l"(u0), "=l"(u1), "=l"(u2), "=l"(u3) : "l"(p));
    F8 r;
    *reinterpret_cast<uint64_t*>(&r.f[0]) = u0;
    *reinterpret_cast<uint64_t*>(&r.f[2]) = u1;
    *reinterpret_cast<uint64_t*>(&r.f[4]) = u2;
    *reinterpret_cast<uint64_t*>(&r.f[6]) = u3;
    return r;
}

__device__ __forceinline__ void stg32(float* p, const float* v) {
    const uint64_t* u = reinterpret_cast<const uint64_t*>(v);
    asm volatile("st.global.v4.b64 [%0], {%1,%2,%3,%4};"
                 :: "l"(p), "l"(u[0]), "l"(u[1]), "l"(u[2]), "l"(u[3])
                 : "memory");
}

__global__ __launch_bounds__(224) void roi_pool_kernel(
    const float*  __restrict__ img,    // (H*W*256) floats
    const float4* __restrict__ rois4,  // (300) float4 = (x0,y0,w,h)
    float*        __restrict__ out)    // (300*49*256) floats
{
    const int roi = blockIdx.y;
    const int px  = blockIdx.x;      // 0..6
    const int py  = threadIdx.y;     // 0..6 (one warp per pool row)

    const float4 rp = __ldg(rois4 + roi);
    const int x0 = (int)rp.x;
    const int y0 = (int)rp.y;
    const int w  = (int)rp.z;
    const int h  = (int)rp.w;

    // Sample coords, exactly as reference: c = (i+0.5)*(size/P) - 0.5, clamped.
    float cy = ((float)py + 0.5f) * ((float)h / (float)POOL) - 0.5f;
    cy = fminf(fmaxf(cy, 0.0f), (float)h - 1.0f);
    float cx = ((float)px + 0.5f) * ((float)w / (float)POOL) - 0.5f;
    cx = fminf(fmaxf(cx, 0.0f), (float)w - 1.0f);

    const int ylo = (int)cy;
    const int xlo = (int)cx;
    const int yhi = min(ylo + 1, h - 1);
    const int xhi = min(xlo + 1, w - 1);
    const float fy = cy - (float)ylo;
    const float fx = cx - (float)xlo;

    const float w00 = (1.0f - fy) * (1.0f - fx);
    const float w01 = (1.0f - fy) * fx;
    const float w10 = fy * (1.0f - fx);
    const float w11 = fy * fx;

    // Float offsets fit in 32 bits (img = 2^28 floats).
    const unsigned r_lo = (unsigned)(y0 + ylo) * (IMG_W * CF);
    const unsigned r_hi = (unsigned)(y0 + yhi) * (IMG_W * CF);
    const unsigned cL   = (unsigned)(x0 + xlo) * CF;
    const unsigned cR   = (unsigned)(x0 + xhi) * CF;

    const unsigned c8 = (unsigned)threadIdx.x * 8;   // lane * 8 floats (32B)

    const F8 v00 = ldg_keep32(img + r_lo + cL + c8);
    const F8 v01 = ldg_keep32(img + r_lo + cR + c8);
    const F8 v10 = ldg_keep32(img + r_hi + cL + c8);
    const F8 v11 = ldg_keep32(img + r_hi + cR + c8);

    float o[8];
    #pragma unroll
    for (int i = 0; i < 8; i++)
        o[i] = v00.f[i] * w00 + v01.f[i] * w01 + v10.f[i] * w10 + v11.f[i] * w11;

    stg32(out + ((unsigned)roi * (POOL * POOL) + (unsigned)(py * POOL + px)) * CF + c8, o);
}

extern "C" void kernel_launch(void* const* d_in, const int* in_sizes, int n_in,
                              void* d_out, int out_size)
{
    const float*  img   = (const float*)d_in[0];
    const float4* rois4 = (const float4*)d_in[1];
    float* o = (float*)d_out;

    dim3 block(32, POOL, 1);    // 32 lanes x 7 pool rows = 224 (exact fit)
    dim3 grid(POOL, 300, 1);    // px x roi
    roi_pool_kernel<<<grid, block>>>(img, rois4, o);
}